// round 4
// baseline (speedup 1.0000x reference)
#include <cuda_runtime.h>
#include <math.h>

#define Bb     4
#define NN     65536
#define CC     192
#define NHEADS 6
#define HC     32
#define BN     (Bb * NN)

typedef unsigned long long u64;

// -------- packed f32x2 helpers (sm_100+) -----------------------------------
__device__ __forceinline__ u64 pack2(float x, float y) {
    u64 r; asm("mov.b64 %0, {%1,%2};" : "=l"(r) : "f"(x), "f"(y)); return r;
}
__device__ __forceinline__ u64 pack2dup(float x) {
    u64 r; asm("mov.b64 %0, {%1,%1};" : "=l"(r) : "f"(x)); return r;
}
__device__ __forceinline__ float2 unpack2(u64 v) {
    float2 r; asm("mov.b64 {%0,%1}, %2;" : "=f"(r.x), "=f"(r.y) : "l"(v)); return r;
}
__device__ __forceinline__ void fma2(u64& d, u64 a, u64 b) {
    asm("fma.rn.f32x2 %0, %1, %2, %0;" : "+l"(d) : "l"(a), "l"(b));
}

// -------- scratch (static device globals; no allocation anywhere) ----------
__device__ float g_q   [(size_t)BN * CC];           // q, head-grouped channels
__device__ float g_ret [(size_t)BN * CC];           // attn + x
__device__ float g_h   [(size_t)BN * CC];           // gelu(o1)
__device__ float g_kv  [Bb * NHEADS * HC * HC];     // sum_n k_d * v_e
__device__ float g_qkvT[192 * 576];                 // qkv_w transposed: [k][j]
__device__ float g_o1T [192 * 192];                 // o1_w transposed:  [k][j]
__device__ float g_o2T [192 * 192];                 // o2_w transposed:  [k][j]

// ---------------------------------------------------------------------------
__global__ __launch_bounds__(1024) void k_zero_kv() {
    int i = blockIdx.x * 1024 + threadIdx.x;
    if (i < Bb * NHEADS * HC * HC) g_kv[i] = 0.0f;
}

// One-time weight transposes (k-major), coalesced reads.
__global__ __launch_bounds__(256) void k_wT(const float* __restrict__ qkv_w,
                                            const float* __restrict__ o1_w,
                                            const float* __restrict__ o2_w) {
    int i = blockIdx.x * 256 + threadIdx.x;
    const int A = 576 * 192, B2 = 192 * 192;
    if (i < A) {
        int j = i / 192, k = i - j * 192;
        g_qkvT[k * 576 + j] = qkv_w[i];
    } else if (i < A + B2) {
        int t = i - A; int j = t / 192, k = t - j * 192;
        g_o1T[k * 192 + j] = o1_w[t];
    } else if (i < A + 2 * B2) {
        int t = i - A - B2; int j = t / 192, k = t - j * 192;
        g_o2T[k * 192 + j] = o2_w[t];
    }
}

// ---------------------------------------------------------------------------
// Kernel 1: per (b, 128-row chunk), 512 threads. Loops over 6 heads:
//   GEMM x[128,192] @ Wh^T[192,96] + bias -> [q|k|v] tile in SMEM,
//   LayerNorm(k), LayerNorm(v) (ddof=1, /(std+eps)),
//   q -> g_q, local 32x32 k^T v outer-product -> atomicAdd g_kv.
// SMEM: xs[128][196] + ws[192][100] + ot[128][100] = 228352 B
// Strides 100 so k*100 + 4*j4 is 16B-aligned for float4 staging.
// Thread tile: 4 rows x 3 column-PAIRS (j = 2*tx + 32*c), packed f32x2 math.
// ---------------------------------------------------------------------------
__global__ __launch_bounds__(512) void k_qkv(
    const float* __restrict__ x, const float* __restrict__ qkv_b,
    const float* __restrict__ klw, const float* __restrict__ klb,
    const float* __restrict__ vlw, const float* __restrict__ vlb)
{
    extern __shared__ float sm[];
    float* xs = sm;                  // [128][196]
    float* ws = sm + 128 * 196;      // [192][100]  (ws[k][j] = W[96h+j][k])
    float* ot = ws + 192 * 100;      // [128][100]

    const int tid = threadIdx.x;
    const int tx  = tid & 15;
    const int ty  = tid >> 4;        // 0..31
    const int b   = blockIdx.y;
    const int n0  = blockIdx.x * 128;

    // load x tile (contiguous 128*192 floats), vectorized
    const float4* xsrc = reinterpret_cast<const float4*>(x + ((size_t)b * NN + n0) * CC);
    for (int i = tid; i < 128 * 48; i += 512) {
        int m = i / 48, k4 = i - m * 48;
        reinterpret_cast<float4*>(xs + m * 196)[k4] = xsrc[i];
    }

    for (int h = 0; h < NHEADS; ++h) {
        __syncthreads();  // prev head's readers of ws/ot done
        // stage head weight slice (already k-major): float4, conflict-free
        const float* wsrc = g_qkvT + 96 * h;
        for (int i = tid; i < 192 * 24; i += 512) {
            int k = i / 24, j4 = i - k * 24;
            *reinterpret_cast<float4*>(ws + k * 100 + 4 * j4)
                = *reinterpret_cast<const float4*>(wsrc + k * 576 + 4 * j4);
        }
        u64 bias3[3];
        #pragma unroll
        for (int c = 0; c < 3; ++c) {
            int j = 2 * tx + 32 * c;
            bias3[c] = pack2(qkv_b[96 * h + j], qkv_b[96 * h + j + 1]);
        }
        __syncthreads();

        // GEMM: 128x96, thread tile 4 rows x 3 col-pairs, packed f32x2
        u64 acc[4][3];
        #pragma unroll
        for (int r = 0; r < 4; ++r)
            #pragma unroll
            for (int c = 0; c < 3; ++c) acc[r][c] = 0ull;

        #pragma unroll 4
        for (int k = 0; k < 192; ++k) {
            u64 a2[4], wv[3];
            const u64* wp = reinterpret_cast<const u64*>(ws + k * 100);
            #pragma unroll
            for (int c = 0; c < 3; ++c) wv[c] = wp[tx + 16 * c];
            #pragma unroll
            for (int r = 0; r < 4; ++r) a2[r] = pack2dup(xs[(ty * 4 + r) * 196 + k]);
            #pragma unroll
            for (int r = 0; r < 4; ++r)
                #pragma unroll
                for (int c = 0; c < 3; ++c) fma2(acc[r][c], a2[r], wv[c]);
        }
        #pragma unroll
        for (int r = 0; r < 4; ++r)
            #pragma unroll
            for (int c = 0; c < 3; ++c) {
                float2 v = unpack2(acc[r][c]);
                float2 bb = unpack2(bias3[c]);
                *reinterpret_cast<float2*>(ot + (ty * 4 + r) * 100 + 2 * tx + 32 * c)
                    = make_float2(v.x + bb.x, v.y + bb.y);
            }
        __syncthreads();

        // LayerNorm: threads 0..127 do k of row tid; 128..255 do v of row tid-128
        if (tid < 256) {
            int row = tid & 127;
            int isv = tid >> 7;
            float* p = ot + row * 100 + 32 + isv * 32;
            const float* lw = (isv ? vlw : klw) + h * HC;
            const float* lb = (isv ? vlb : klb) + h * HC;
            float s = 0.0f;
            #pragma unroll
            for (int i = 0; i < 32; ++i) s += p[i];
            float mean = s * (1.0f / 32.0f);
            float vs = 0.0f;
            #pragma unroll
            for (int i = 0; i < 32; ++i) { float d = p[i] - mean; vs = fmaf(d, d, vs); }
            float inv = 1.0f / (sqrtf(vs * (1.0f / 31.0f)) + 1e-5f);
            #pragma unroll
            for (int i = 0; i < 32; ++i)
                p[i] = fmaf(lw[i], (p[i] - mean) * inv, lb[i]);
        }
        __syncthreads();

        // store q (head-grouped channel layout: channel = h*32 + j)
        float* qdst = g_q + ((size_t)b * NN + n0) * CC + h * HC;
        for (int i = tid; i < 128 * 16; i += 512) {
            int m = i >> 4, j2 = i & 15;
            *reinterpret_cast<float2*>(qdst + (size_t)m * CC + 2 * j2)
                = *reinterpret_cast<const float2*>(ot + m * 100 + 2 * j2);
        }

        // local kv outer-product, ALL 512 threads: thread owns (d, e0..e0+1)
        {
            int d  = tid >> 4;          // 0..31
            int e0 = (tid & 15) << 1;   // 0,2,...,30
            u64 s01 = 0ull;
            for (int r = 0; r < 128; ++r) {
                u64 kk = pack2dup(ot[r * 100 + 32 + d]);
                u64 vv = *reinterpret_cast<const u64*>(ot + r * 100 + 64 + e0);
                fma2(s01, kk, vv);
            }
            float2 a = unpack2(s01);
            float* dst = g_kv + (((b * NHEADS) + h) * HC + d) * HC + e0;
            atomicAdd(dst + 0, a.x);
            atomicAdd(dst + 1, a.y);
        }
    }
}

// ---------------------------------------------------------------------------
// Kernel 2: ret = x + q @ (kv / N).  32 rows/block, 384 threads.
// Within each half of 192 threads: warp w handles head w;
// thread tile 4 rows x 2 e-pairs, packed f32x2.
// ---------------------------------------------------------------------------
__global__ __launch_bounds__(384) void k_attn(const float* __restrict__ x)
{
    __shared__ float kvs[NHEADS * HC * HC];  // [h][d][e]   6144 floats
    __shared__ float qs[32 * CC];            //             6144 floats

    const int tid = threadIdx.x;
    const int R0  = blockIdx.x * 32;
    const int b   = R0 >> 16;  // 65536 rows per batch; 32 | 65536

    for (int i = tid; i < NHEADS * HC * HC; i += 384)
        kvs[i] = g_kv[b * (NHEADS * HC * HC) + i] * (1.0f / (float)NN);
    const float* qsrc = g_q + (size_t)R0 * CC;
    for (int i = tid; i < 32 * CC; i += 384) qs[i] = qsrc[i];
    __syncthreads();

    const int half = tid / 192;      // 0 or 1: rows [0,16) or [16,32)
    const int t    = tid - half * 192;
    const int h    = t >> 5;
    const int t32  = t & 31;
    const int rq   = t32 >> 3;
    const int eq   = t32 & 7;
    const int rbase = half * 16 + rq * 4;

    u64 acc[4][2];
    #pragma unroll
    for (int i = 0; i < 4; ++i) { acc[i][0] = 0ull; acc[i][1] = 0ull; }

    const float* qb = qs + rbase * CC + h * HC;
    #pragma unroll 4
    for (int d = 0; d < 32; ++d) {
        const u64* kvp = reinterpret_cast<const u64*>(kvs + (h * HC + d) * HC + eq * 4);
        u64 kv01 = kvp[0], kv23 = kvp[1];
        #pragma unroll
        for (int i = 0; i < 4; ++i) {
            u64 qd = pack2dup(qb[i * CC + d]);
            fma2(acc[i][0], qd, kv01);
            fma2(acc[i][1], qd, kv23);
        }
    }
    #pragma unroll
    for (int i = 0; i < 4; ++i) {
        size_t g = ((size_t)(R0 + rbase + i)) * CC + h * HC + eq * 4;
        float4 xv = *reinterpret_cast<const float4*>(x + g);
        float2 a = unpack2(acc[i][0]), c2 = unpack2(acc[i][1]);
        float4 o;
        o.x = a.x + xv.x;
        o.y = a.y + xv.y;
        o.z = c2.x + xv.z;
        o.w = c2.y + xv.w;
        *reinterpret_cast<float4*>(g_ret + g) = o;
    }
}

// ---------------------------------------------------------------------------
// 192x192 GEMM body: 64 rows/block, 512 threads, full (pre-transposed) weight
// in SMEM (stride 196 so every k-row is 16B-aligned), thread tile
// 2 rows x 3 column-QUADS (j = 4*tx + 64*c), LDS.128 weight reads.
// GELU=true: out = gelu(acc+bias); else out = acc + bias + xres.
// SMEM: xs[64][196] + ws[192][196] = 200704 B
// ---------------------------------------------------------------------------
template <bool GELU>
__device__ __forceinline__ void mlp_body(
    const float* __restrict__ in, const float* __restrict__ wT,
    const float* __restrict__ bias, const float* __restrict__ xres,
    float* __restrict__ out, float* sm)
{
    float* xs = sm;                 // [64][196]
    float* ws = sm + 64 * 196;      // [192][196]

    const int tid = threadIdx.x;
    const int tx  = tid & 15;
    const int ty  = tid >> 4;       // 0..31
    const int R0  = blockIdx.x * 64;

    const float4* isrc = reinterpret_cast<const float4*>(in + (size_t)R0 * CC);
    for (int i = tid; i < 64 * 48; i += 512) {
        int m = i / 48, k4 = i - m * 48;
        reinterpret_cast<float4*>(xs + m * 196)[k4] = isrc[i];
    }
    // stage transposed weight: float4, conflict-free
    for (int i = tid; i < 192 * 48; i += 512) {
        int k = i / 48, j4 = i - k * 48;
        *reinterpret_cast<float4*>(ws + k * 196 + 4 * j4)
            = *reinterpret_cast<const float4*>(wT + k * 192 + 4 * j4);
    }
    float4 b4[3];
    #pragma unroll
    for (int c = 0; c < 3; ++c)
        b4[c] = *reinterpret_cast<const float4*>(bias + 4 * tx + 64 * c);
    __syncthreads();

    u64 acc[2][3][2];
    #pragma unroll
    for (int r = 0; r < 2; ++r)
        #pragma unroll
        for (int c = 0; c < 3; ++c) { acc[r][c][0] = 0ull; acc[r][c][1] = 0ull; }

    #pragma unroll 4
    for (int k = 0; k < 192; ++k) {
        ulonglong2 wv[3];
        u64 a2[2];
        #pragma unroll
        for (int c = 0; c < 3; ++c)
            wv[c] = *reinterpret_cast<const ulonglong2*>(ws + k * 196 + 4 * tx + 64 * c);
        #pragma unroll
        for (int r = 0; r < 2; ++r) a2[r] = pack2dup(xs[(ty * 2 + r) * 196 + k]);
        #pragma unroll
        for (int r = 0; r < 2; ++r)
            #pragma unroll
            for (int c = 0; c < 3; ++c) {
                fma2(acc[r][c][0], a2[r], wv[c].x);
                fma2(acc[r][c][1], a2[r], wv[c].y);
            }
    }

    #pragma unroll
    for (int r = 0; r < 2; ++r) {
        size_t row = (size_t)(R0 + ty * 2 + r);
        #pragma unroll
        for (int c = 0; c < 3; ++c) {
            int j = 4 * tx + 64 * c;
            float2 vlo = unpack2(acc[r][c][0]);
            float2 vhi = unpack2(acc[r][c][1]);
            float v0 = vlo.x + b4[c].x;
            float v1 = vlo.y + b4[c].y;
            float v2 = vhi.x + b4[c].z;
            float v3 = vhi.y + b4[c].w;
            size_t g = row * CC + j;
            float4 o;
            if (GELU) {
                o.x = 0.5f * v0 * (1.0f + erff(v0 * 0.70710678118654752440f));
                o.y = 0.5f * v1 * (1.0f + erff(v1 * 0.70710678118654752440f));
                o.z = 0.5f * v2 * (1.0f + erff(v2 * 0.70710678118654752440f));
                o.w = 0.5f * v3 * (1.0f + erff(v3 * 0.70710678118654752440f));
            } else {
                float4 xr = *reinterpret_cast<const float4*>(xres + g);
                o.x = v0 + xr.x;
                o.y = v1 + xr.y;
                o.z = v2 + xr.z;
                o.w = v3 + xr.w;
            }
            *reinterpret_cast<float4*>(out + g) = o;
        }
    }
}

__global__ __launch_bounds__(512) void k_mlp1(const float* __restrict__ b)
{
    extern __shared__ float sm[];
    mlp_body<true>(g_ret, g_o1T, b, nullptr, g_h, sm);
}

__global__ __launch_bounds__(512) void k_mlp2(const float* __restrict__ b,
                                              const float* __restrict__ x,
                                              float* __restrict__ out)
{
    extern __shared__ float sm[];
    mlp_body<false>(g_h, g_o2T, b, x, out, sm);
}

// ---------------------------------------------------------------------------
extern "C" void kernel_launch(void* const* d_in, const int* in_sizes, int n_in,
                              void* d_out, int out_size)
{
    (void)in_sizes; (void)n_in; (void)out_size;
    const float* x     = (const float*)d_in[0];
    const float* qkv_w = (const float*)d_in[1];
    const float* qkv_b = (const float*)d_in[2];
    const float* o1_w  = (const float*)d_in[3];
    const float* o1_b  = (const float*)d_in[4];
    const float* o2_w  = (const float*)d_in[5];
    const float* o2_b  = (const float*)d_in[6];
    const float* klw   = (const float*)d_in[7];
    const float* klb   = (const float*)d_in[8];
    const float* vlw   = (const float*)d_in[9];
    const float* vlb   = (const float*)d_in[10];
    float* out = (float*)d_out;

    const int smem_qkv = (128 * 196 + 192 * 100 + 128 * 100) * 4;  // 228352
    const int smem_mlp = (64 * 196 + 192 * 196) * 4;               // 200704
    cudaFuncSetAttribute(k_qkv,  cudaFuncAttributeMaxDynamicSharedMemorySize, smem_qkv);
    cudaFuncSetAttribute(k_mlp1, cudaFuncAttributeMaxDynamicSharedMemorySize, smem_mlp);
    cudaFuncSetAttribute(k_mlp2, cudaFuncAttributeMaxDynamicSharedMemorySize, smem_mlp);

    k_zero_kv<<<24, 1024>>>();
    k_wT<<<720, 256>>>(qkv_w, o1_w, o2_w);   // 184320 elements

    dim3 g1(NN / 128, Bb);
    k_qkv<<<g1, 512, smem_qkv>>>(x, qkv_b, klw, klb, vlw, vlb);

    k_attn<<<BN / 32, 384>>>(x);

    k_mlp1<<<BN / 64, 512, smem_mlp>>>(o1_b);
    k_mlp2<<<BN / 64, 512, smem_mlp>>>(o2_b, x, out);
}

// round 10
// speedup vs baseline: 1.7047x; 1.7047x over previous
#include <cuda_runtime.h>
#include <cuda_bf16.h>
#include <cstdint>
#include <math.h>

#define Bb     4
#define NN     65536
#define CC     192
#define NHEADS 6
#define HC     32
#define BN     (Bb * NN)
#define NBLK   512            /* qkv row-chunks per batch: 65536/128 */

typedef unsigned long long u64;
typedef unsigned int       u32;

// ---------------- packed f32x2 helpers (attn / kv outer) -------------------
__device__ __forceinline__ u64 pack2dup(float x) {
    u64 r; asm("mov.b64 %0, {%1,%1};" : "=l"(r) : "f"(x)); return r;
}
__device__ __forceinline__ float2 unpack2(u64 v) {
    float2 r; asm("mov.b64 {%0,%1}, %2;" : "=f"(r.x), "=f"(r.y) : "l"(v)); return r;
}
__device__ __forceinline__ void fma2(u64& d, u64 a, u64 b) {
    asm("fma.rn.f32x2 %0, %1, %2, %0;" : "+l"(d) : "l"(a), "l"(b));
}
__device__ __forceinline__ void split_bf16(float v, __nv_bfloat16& h, __nv_bfloat16& l) {
    h = __float2bfloat16(v);
    l = __float2bfloat16(v - __bfloat162float(h));
}
__device__ __forceinline__ u32 packbf(float a, float b) {
    __nv_bfloat162 t = __floats2bfloat162_rn(a, b);   // low half = a
    return *reinterpret_cast<u32*>(&t);
}

// mma.sync m16n8k16 row.col bf16 -> f32 accum (sm_80+ base feature)
__device__ __forceinline__ void mma_bf16(float* d, const u32* a, u32 b0, u32 b1) {
    asm volatile(
        "mma.sync.aligned.m16n8k16.row.col.f32.bf16.bf16.f32 "
        "{%0,%1,%2,%3}, {%4,%5,%6,%7}, {%8,%9}, {%0,%1,%2,%3};"
        : "+f"(d[0]), "+f"(d[1]), "+f"(d[2]), "+f"(d[3])
        : "r"(a[0]), "r"(a[1]), "r"(a[2]), "r"(a[3]), "r"(b0), "r"(b1));
}

// ---------------- global scratch -------------------------------------------
__device__ float g_q  [(size_t)BN * CC];
__device__ float g_kv [Bb * NHEADS * HC * HC];
__device__ float g_kvp[(size_t)Bb * NHEADS * NBLK * HC * HC];  // per-block partials
__device__ __nv_bfloat16 g_ret_hi[(size_t)BN * CC];
__device__ __nv_bfloat16 g_ret_lo[(size_t)BN * CC];
__device__ __nv_bfloat16 g_h_hi  [(size_t)BN * CC];
__device__ __nv_bfloat16 g_h_lo  [(size_t)BN * CC];
// B fragments, layout [..gnt..][kt][lane][hl] so hi+lo load as one LDG.128.
// u64 = {b0pair(k,k+1), b1pair(k+8,k+9)}
__device__ u64 g_fq[6 * 12 * 12 * 32 * 2];   // [h][gnt12][kt12][lane][hl]
__device__ u64 g_f1[24 * 12 * 32 * 2];       // [gnt24][kt12][lane][hl]
__device__ u64 g_f2[24 * 12 * 32 * 2];

// ---------------------------------------------------------------------------
// prep: build B fragments (hi / lo split) for all three weight matrices.
__global__ __launch_bounds__(256) void k_prep(const float* __restrict__ qkv_w,
                                              const float* __restrict__ o1_w,
                                              const float* __restrict__ o2_w) {
    int i = blockIdx.x * 256 + threadIdx.x;
    const int NQ = 6 * 12 * 12 * 32 * 2;      // 55296
    const int NM = 24 * 12 * 32 * 2;          // 18432
    const float* W; u64* dst; int j, k, hl;
    if (i < NQ) {
        hl = i & 1; int lane = (i >> 1) & 31; int q = i >> 6;
        int kt = q % 12; q /= 12;
        int gnt = q % 12; int h = q / 12;
        j = 96 * h + gnt * 8 + (lane >> 2);
        k = kt * 16 + 2 * (lane & 3);
        W = qkv_w; dst = g_fq + i;
    } else if (i < NQ + NM) {
        int t = i - NQ;
        hl = t & 1; int lane = (t >> 1) & 31; int q = t >> 6;
        int kt = q % 12; int gnt = q / 12;
        j = gnt * 8 + (lane >> 2);
        k = kt * 16 + 2 * (lane & 3);
        W = o1_w; dst = g_f1 + t;
    } else if (i < NQ + 2 * NM) {
        int t = i - NQ - NM;
        hl = t & 1; int lane = (t >> 1) & 31; int q = t >> 6;
        int kt = q % 12; int gnt = q / 12;
        j = gnt * 8 + (lane >> 2);
        k = kt * 16 + 2 * (lane & 3);
        W = o2_w; dst = g_f2 + t;
    } else return;

    float w[4] = { W[(size_t)j * 192 + k],     W[(size_t)j * 192 + k + 1],
                   W[(size_t)j * 192 + k + 8], W[(size_t)j * 192 + k + 9] };
    float v[4];
    #pragma unroll
    for (int e = 0; e < 4; ++e) {
        __nv_bfloat16 hb, lb; split_bf16(w[e], hb, lb);
        v[e] = hl ? __bfloat162float(lb) : __bfloat162float(hb);
    }
    u32 p0 = packbf(v[0], v[1]);
    u32 p1 = packbf(v[2], v[3]);
    *dst = (u64)p0 | ((u64)p1 << 32);
}

// deterministic kv reduction: one block per (b,h); thread = (d,e); fixed order
__global__ __launch_bounds__(1024) void k_kvred() {
    int bh = blockIdx.x;            // 0..23
    int de = threadIdx.x;           // 0..1023
    const float* src = g_kvp + (size_t)bh * NBLK * 1024 + de;
    float s = 0.0f;
    for (int i = 0; i < NBLK; ++i) s += src[(size_t)i * 1024];
    g_kv[bh * 1024 + de] = s;
}

// ====================== k_qkv: mma.sync QKV + LN + kv ======================
// 512 threads, 128 rows/block. Warp w: rows (w&7)*16, col-half ch=(w>>3)*48.
// SMEM floats: AsHi[128][100](u32) | AsLo | kvbuf[128][66] | sqb[576] | sln[768]
#define QS_TOT ((12800 + 12800 + 128 * 66 + 576 + 768) * 4)   /* 141568 B */

__global__ __launch_bounds__(512) void k_qkv(
    const float* __restrict__ x, const float* __restrict__ qkv_b,
    const float* __restrict__ klw, const float* __restrict__ klb,
    const float* __restrict__ vlw, const float* __restrict__ vlb)
{
    extern __shared__ float smf[];
    u32*  AsHi  = (u32*)smf;                 // [128][100]
    u32*  AsLo  = AsHi + 12800;
    float* kvbuf = smf + 25600;              // [128][66]
    float* sqb   = kvbuf + 128 * 66;         // 576
    float* sln   = sqb + 576;                // klw|klb|vlw|vlb each 192

    const int tid  = threadIdx.x;
    const int lane = tid & 31, warp = tid >> 5;
    const int rg = warp & 7, ch = warp >> 3;
    const int tig = lane & 3, gid = lane >> 2;
    const size_t R0 = (size_t)blockIdx.x * 128;
    const int b   = blockIdx.x >> 9;         // 512 chunks per batch
    const int blk = blockIdx.x & (NBLK - 1);

    for (int i = tid; i < 576; i += 512) sqb[i] = qkv_b[i];
    for (int i = tid; i < 192; i += 512) {
        sln[i] = klw[i]; sln[192 + i] = klb[i];
        sln[384 + i] = vlw[i]; sln[576 + i] = vlb[i];
    }
    // stage x -> packed bf16 hi/lo pairs
    const float2* xsrc = reinterpret_cast<const float2*>(x + R0 * CC);
    for (int i = tid; i < 128 * 96; i += 512) {
        int r = i / 96, c = i - r * 96;
        float2 v = xsrc[i];
        __nv_bfloat16 h0, l0, h1, l1;
        split_bf16(v.x, h0, l0); split_bf16(v.y, h1, l1);
        AsHi[r * 100 + c] = ((u32)__bfloat16_as_ushort(h1) << 16) | __bfloat16_as_ushort(h0);
        AsLo[r * 100 + c] = ((u32)__bfloat16_as_ushort(l1) << 16) | __bfloat16_as_ushort(l0);
    }
    __syncthreads();

    const int arow = rg * 16 + gid;
    const u32* AH0 = AsHi + arow * 100;
    const u32* AH8 = AsHi + (arow + 8) * 100;
    const u32* AL0 = AsLo + arow * 100;
    const u32* AL8 = AsLo + (arow + 8) * 100;

    for (int h = 0; h < NHEADS; ++h) {
        float acc[6][4];
        #pragma unroll
        for (int nt = 0; nt < 6; ++nt)
            #pragma unroll
            for (int e = 0; e < 4; ++e) acc[nt][e] = 0.0f;

        const ulonglong2* fh =
            reinterpret_cast<const ulonglong2*>(g_fq + (size_t)h * (12 * 12 * 32 * 2));
        for (int kt = 0; kt < 12; ++kt) {
            int kb = kt * 8 + tig;
            u32 ah[4] = { AH0[kb], AH8[kb], AH0[kb + 4], AH8[kb + 4] };
            u32 al[4] = { AL0[kb], AL8[kb], AL0[kb + 4], AL8[kb + 4] };
            #pragma unroll
            for (int nt = 0; nt < 6; ++nt) {
                int gnt = ch * 6 + nt;
                ulonglong2 f = fh[(gnt * 12 + kt) * 32 + lane];
                u32 bh0 = (u32)f.x, bh1 = (u32)(f.x >> 32);
                u32 bl0 = (u32)f.y, bl1 = (u32)(f.y >> 32);
                mma_bf16(acc[nt], ah, bh0, bh1);
                mma_bf16(acc[nt], ah, bl0, bl1);
                mma_bf16(acc[nt], al, bh0, bh1);
            }
        }
        __syncthreads();   // previous head's kv-outer finished reading kvbuf

        // epilogue: q -> global, k/v(+bias) -> kvbuf
        #pragma unroll
        for (int nt = 0; nt < 6; ++nt) {
            int col = ch * 48 + nt * 8 + 2 * tig;
            float b0 = sqb[96 * h + col], b1 = sqb[96 * h + col + 1];
            float c0 = acc[nt][0] + b0, c1 = acc[nt][1] + b1;
            float c2 = acc[nt][2] + b0, c3 = acc[nt][3] + b1;
            if (col < 32) {
                float* q0 = g_q + (R0 + arow) * CC + h * HC + col;
                float* q8 = g_q + (R0 + arow + 8) * CC + h * HC + col;
                *reinterpret_cast<float2*>(q0) = make_float2(c0, c1);
                *reinterpret_cast<float2*>(q8) = make_float2(c2, c3);
            } else {
                int kc = col - 32;
                *reinterpret_cast<float2*>(kvbuf + arow * 66 + kc)       = make_float2(c0, c1);
                *reinterpret_cast<float2*>(kvbuf + (arow + 8) * 66 + kc) = make_float2(c2, c3);
            }
        }
        __syncthreads();

        // LayerNorm (ddof=1, /(std+eps)): threads 0-127 k rows, 128-255 v rows
        if (tid < 256) {
            int row = tid & 127, isv = tid >> 7;
            float* p = kvbuf + row * 66 + isv * 32;
            const float* lw = sln + isv * 384 + h * HC;
            const float* lb = lw + 192;
            float s = 0.0f;
            #pragma unroll
            for (int i = 0; i < 32; ++i) s += p[i];
            float mean = s * (1.0f / 32.0f), vs = 0.0f;
            #pragma unroll
            for (int i = 0; i < 32; ++i) { float d = p[i] - mean; vs = fmaf(d, d, vs); }
            float inv = 1.0f / (sqrtf(vs * (1.0f / 31.0f)) + 1e-5f);
            #pragma unroll
            for (int i = 0; i < 32; ++i)
                p[i] = fmaf(lw[i], (p[i] - mean) * inv, lb[i]);
        }
        __syncthreads();

        // kv outer product over 128 rows, all 512 threads: (d, e0..e0+1)
        // -> deterministic per-block partial (plain store, no atomics)
        {
            int d  = tid >> 4;
            int e0 = (tid & 15) << 1;
            u64 s01 = 0ull;
            for (int r = 0; r < 128; ++r) {
                u64 kk = pack2dup(kvbuf[r * 66 + d]);
                u64 vv = *reinterpret_cast<const u64*>(kvbuf + r * 66 + 32 + e0);
                fma2(s01, kk, vv);
            }
            float2 a = unpack2(s01);
            float* dst = g_kvp + ((size_t)((b * NHEADS) + h) * NBLK + blk) * 1024
                       + d * HC + e0;
            *reinterpret_cast<float2*>(dst) = make_float2(a.x, a.y);
        }
    }
}

// ====================== k_attn (round-4 passing body, bf16 hi/lo out) ======
__global__ __launch_bounds__(384) void k_attn(const float* __restrict__ x)
{
    __shared__ float kvs[NHEADS * HC * HC];
    __shared__ float qs[32 * CC];

    const int tid = threadIdx.x;
    const int R0  = blockIdx.x * 32;
    const int b   = R0 >> 16;

    for (int i = tid; i < NHEADS * HC * HC; i += 384)
        kvs[i] = g_kv[b * (NHEADS * HC * HC) + i] * (1.0f / (float)NN);
    const float* qsrc = g_q + (size_t)R0 * CC;
    for (int i = tid; i < 32 * CC; i += 384) qs[i] = qsrc[i];
    __syncthreads();

    const int half = tid / 192;
    const int t    = tid - half * 192;
    const int h    = t >> 5;
    const int t32  = t & 31;
    const int rq   = t32 >> 3;
    const int eq   = t32 & 7;
    const int rbase = half * 16 + rq * 4;

    u64 acc[4][2];
    #pragma unroll
    for (int i = 0; i < 4; ++i) { acc[i][0] = 0ull; acc[i][1] = 0ull; }

    const float* qb = qs + rbase * CC + h * HC;
    #pragma unroll 4
    for (int d = 0; d < 32; ++d) {
        const u64* kvp = reinterpret_cast<const u64*>(kvs + (h * HC + d) * HC + eq * 4);
        u64 kv01 = kvp[0], kv23 = kvp[1];
        #pragma unroll
        for (int i = 0; i < 4; ++i) {
            u64 qd = pack2dup(qb[i * CC + d]);
            fma2(acc[i][0], qd, kv01);
            fma2(acc[i][1], qd, kv23);
        }
    }
    #pragma unroll
    for (int i = 0; i < 4; ++i) {
        size_t g = ((size_t)(R0 + rbase + i)) * CC + h * HC + eq * 4;
        float4 xv = *reinterpret_cast<const float4*>(x + g);
        float2 a = unpack2(acc[i][0]), c2 = unpack2(acc[i][1]);
        float o0 = a.x + xv.x, o1 = a.y + xv.y, o2 = c2.x + xv.z, o3 = c2.y + xv.w;
        __nv_bfloat16 h0, l0, h1, l1, h2, l2, h3, l3;
        split_bf16(o0, h0, l0); split_bf16(o1, h1, l1);
        split_bf16(o2, h2, l2); split_bf16(o3, h3, l3);
        *reinterpret_cast<__nv_bfloat162*>(g_ret_hi + g)     = __halves2bfloat162(h0, h1);
        *reinterpret_cast<__nv_bfloat162*>(g_ret_hi + g + 2) = __halves2bfloat162(h2, h3);
        *reinterpret_cast<__nv_bfloat162*>(g_ret_lo + g)     = __halves2bfloat162(l0, l1);
        *reinterpret_cast<__nv_bfloat162*>(g_ret_lo + g + 2) = __halves2bfloat162(l2, l3);
    }
}

// ====================== MLP GEMMs via mma.sync =============================
// 512 threads, 128 rows x 192 cols per block. Warp w: rows (w&7)*16, cols (w>>3)*96.
#define MS_TOT ((12800 + 12800 + 192) * 4)   /* 103168 B */

__device__ __forceinline__ void mlp_body(
    const __nv_bfloat16* __restrict__ Ahi, const __nv_bfloat16* __restrict__ Alo,
    const u64* __restrict__ frag, const float* __restrict__ bias, bool gelu,
    __nv_bfloat16* __restrict__ OHi, __nv_bfloat16* __restrict__ OLo,
    const float* __restrict__ xres, float* __restrict__ Ofp)
{
    extern __shared__ float smf[];
    u32*  AsHi = (u32*)smf;            // [128][100]
    u32*  AsLo = AsHi + 12800;
    float* sbv = smf + 25600;          // 192 floats

    const int tid  = threadIdx.x;
    const int lane = tid & 31, warp = tid >> 5;
    const int rg = warp & 7, ch = warp >> 3;
    const int tig = lane & 3, gid = lane >> 2;
    const size_t R0 = (size_t)blockIdx.x * 128;

    if (tid < 192) sbv[tid] = bias[tid];
    // stage A hi/lo (bf16 pairs) with uint4 loads
    for (int i = tid; i < 128 * 24; i += 512) {
        int r = i / 24, c4 = i - r * 24;
        uint4 vh = reinterpret_cast<const uint4*>(Ahi + (R0 + r) * CC)[c4];
        uint4 vl = reinterpret_cast<const uint4*>(Alo + (R0 + r) * CC)[c4];
        reinterpret_cast<uint4*>(AsHi + r * 100)[c4] = vh;
        reinterpret_cast<uint4*>(AsLo + r * 100)[c4] = vl;
    }
    __syncthreads();

    const int arow = rg * 16 + gid;
    const u32* AH0 = AsHi + arow * 100;
    const u32* AH8 = AsHi + (arow + 8) * 100;
    const u32* AL0 = AsLo + arow * 100;
    const u32* AL8 = AsLo + (arow + 8) * 100;

    float acc[12][4];
    #pragma unroll
    for (int nt = 0; nt < 12; ++nt)
        #pragma unroll
        for (int e = 0; e < 4; ++e) acc[nt][e] = 0.0f;

    const ulonglong2* fr = reinterpret_cast<const ulonglong2*>(frag);
    for (int kt = 0; kt < 12; ++kt) {
        int kb = kt * 8 + tig;
        u32 ah[4] = { AH0[kb], AH8[kb], AH0[kb + 4], AH8[kb + 4] };
        u32 al[4] = { AL0[kb], AL8[kb], AL0[kb + 4], AL8[kb + 4] };
        #pragma unroll
        for (int nt = 0; nt < 12; ++nt) {
            int gnt = ch * 12 + nt;
            ulonglong2 f = fr[(gnt * 12 + kt) * 32 + lane];
            u32 bh0 = (u32)f.x, bh1 = (u32)(f.x >> 32);
            u32 bl0 = (u32)f.y, bl1 = (u32)(f.y >> 32);
            mma_bf16(acc[nt], ah, bh0, bh1);
            mma_bf16(acc[nt], ah, bl0, bl1);
            mma_bf16(acc[nt], al, bh0, bh1);
        }
    }

    #pragma unroll
    for (int nt = 0; nt < 12; ++nt) {
        int col = ch * 96 + nt * 8 + 2 * tig;
        float b0 = sbv[col], b1 = sbv[col + 1];
        float v0 = acc[nt][0] + b0, v1 = acc[nt][1] + b1;
        float v2 = acc[nt][2] + b0, v3 = acc[nt][3] + b1;
        size_t g0 = (R0 + arow) * CC + col;
        size_t g8 = (R0 + arow + 8) * CC + col;
        if (gelu) {
            float e0 = 0.5f * v0 * (1.0f + erff(v0 * 0.70710678118654752440f));
            float e1 = 0.5f * v1 * (1.0f + erff(v1 * 0.70710678118654752440f));
            float e2 = 0.5f * v2 * (1.0f + erff(v2 * 0.70710678118654752440f));
            float e3 = 0.5f * v3 * (1.0f + erff(v3 * 0.70710678118654752440f));
            __nv_bfloat16 h0, l0, h1, l1, h2, l2, h3, l3;
            split_bf16(e0, h0, l0); split_bf16(e1, h1, l1);
            split_bf16(e2, h2, l2); split_bf16(e3, h3, l3);
            *reinterpret_cast<u32*>(OHi + g0) = ((u32)__bfloat16_as_ushort(h1) << 16) | __bfloat16_as_ushort(h0);
            *reinterpret_cast<u32*>(OLo + g0) = ((u32)__bfloat16_as_ushort(l1) << 16) | __bfloat16_as_ushort(l0);
            *reinterpret_cast<u32*>(OHi + g8) = ((u32)__bfloat16_as_ushort(h3) << 16) | __bfloat16_as_ushort(h2);
            *reinterpret_cast<u32*>(OLo + g8) = ((u32)__bfloat16_as_ushort(l3) << 16) | __bfloat16_as_ushort(l2);
        } else {
            float2 x0 = *reinterpret_cast<const float2*>(xres + g0);
            float2 x8 = *reinterpret_cast<const float2*>(xres + g8);
            *reinterpret_cast<float2*>(Ofp + g0) = make_float2(v0 + x0.x, v1 + x0.y);
            *reinterpret_cast<float2*>(Ofp + g8) = make_float2(v2 + x8.x, v3 + x8.y);
        }
    }
}

__global__ __launch_bounds__(512) void k_mlp1(const float* __restrict__ b) {
    mlp_body(g_ret_hi, g_ret_lo, g_f1, b, true, g_h_hi, g_h_lo, nullptr, nullptr);
}
__global__ __launch_bounds__(512) void k_mlp2(const float* __restrict__ b,
                                              const float* __restrict__ x,
                                              float* __restrict__ out) {
    mlp_body(g_h_hi, g_h_lo, g_f2, b, false, nullptr, nullptr, x, out);
}

// ---------------------------------------------------------------------------
extern "C" void kernel_launch(void* const* d_in, const int* in_sizes, int n_in,
                              void* d_out, int out_size)
{
    (void)in_sizes; (void)n_in; (void)out_size;
    const float* x     = (const float*)d_in[0];
    const float* qkv_w = (const float*)d_in[1];
    const float* qkv_b = (const float*)d_in[2];
    const float* o1_w  = (const float*)d_in[3];
    const float* o1_b  = (const float*)d_in[4];
    const float* o2_w  = (const float*)d_in[5];
    const float* o2_b  = (const float*)d_in[6];
    const float* klw   = (const float*)d_in[7];
    const float* klb   = (const float*)d_in[8];
    const float* vlw   = (const float*)d_in[9];
    const float* vlb   = (const float*)d_in[10];
    float* out = (float*)d_out;

    cudaFuncSetAttribute(k_qkv,  cudaFuncAttributeMaxDynamicSharedMemorySize, QS_TOT);
    cudaFuncSetAttribute(k_mlp1, cudaFuncAttributeMaxDynamicSharedMemorySize, MS_TOT);
    cudaFuncSetAttribute(k_mlp2, cudaFuncAttributeMaxDynamicSharedMemorySize, MS_TOT);

    k_prep<<<360, 256>>>(qkv_w, o1_w, o2_w);   // 92160 fragment items

    k_qkv<<<BN / 128, 512, QS_TOT>>>(x, qkv_b, klw, klb, vlw, vlb);
    k_kvred<<<Bb * NHEADS, 1024>>>();          // deterministic kv reduction
    k_attn<<<BN / 32, 384>>>(x);
    k_mlp1<<<BN / 128, 512, MS_TOT>>>(o1_b);
    k_mlp2<<<BN / 128, 512, MS_TOT>>>(o2_b, x, out);
}